// round 13
// baseline (speedup 1.0000x reference)
#include <cuda_runtime.h>

#define CHUNKS 16
#define RES_DIM 8192
#define NSE 1342177
#define BLOCKS_X 18               // 18*16 = 288 blocks (2/SM, one wave)
#define TPB 1024
#define SMEM_BYTES (2 * RES_DIM * sizeof(float))   // sacc + sstate = 64 KB

// Global accumulator, L2-resident (512 KB). Invariant: zero at kernel_launch
// entry (loader zero-init; the finalizing block re-zeros it every launch).
__device__ float g_gacc[CHUNKS * RES_DIM];
// Per-chunk arrival counters; same zero-at-entry invariant.
__device__ unsigned int g_count[CHUNKS];

// Fused kernel: COO scatter (smem privatization + smem-staged state), vector
// RED flush into g_gacc, and in-kernel finalize by the last-arriving block of
// each chunk (reads only 64 KB: proj + g_gacc slices).
__global__ void __launch_bounds__(TPB, 2)
ptd_scatter_kernel(const float* __restrict__ vals,
                   const int*   __restrict__ rows,
                   const int*   __restrict__ cols,
                   const float* __restrict__ state,
                   const float* __restrict__ proj,
                   float*       __restrict__ out) {
    extern __shared__ float smem[];
    float* sacc   = smem;             // [RES_DIM]
    float* sstate = smem + RES_DIM;   // [RES_DIM]
    __shared__ unsigned int s_last;

    const int chunk = blockIdx.y;
    const size_t base = (size_t)chunk * NSE;

    // Zero accumulator + stage state (both vectorized).
    {
        float4* a4 = reinterpret_cast<float4*>(sacc);
        float4* s4 = reinterpret_cast<float4*>(sstate);
        const float4* st4 = reinterpret_cast<const float4*>(state + (size_t)chunk * RES_DIM);
        #pragma unroll
        for (int i = threadIdx.x; i < RES_DIM / 4; i += TPB) {
            a4[i] = make_float4(0.f, 0.f, 0.f, 0.f);
            s4[i] = st4[i];
        }
    }
    __syncthreads();

    // Alignment split (base not 16B-aligned since NSE is odd).
    const int head = (int)((4 - (base & 3)) & 3);
    const int nvec = (NSE - head) >> 2;
    const int tail = NSE - head - (nvec << 2);

    const float4* __restrict__ v4 = reinterpret_cast<const float4*>(vals + base + head);
    const int4*   __restrict__ r4 = reinterpret_cast<const int4*>(rows + base + head);
    const int4*   __restrict__ c4 = reinterpret_cast<const int4*>(cols + base + head);

    const int stride = BLOCKS_X * TPB;
    int i = blockIdx.x * TPB + threadIdx.x;

    // Main loop, unrolled x2 (8 nnz/thread/iter).
    for (; i + stride < nvec; i += 2 * stride) {
        const int j = i + stride;
        float4 va = __ldcs(v4 + i); float4 vb = __ldcs(v4 + j);
        int4   ca = __ldcs(c4 + i); int4   cb = __ldcs(c4 + j);
        int4   ra = __ldcs(r4 + i); int4   rb = __ldcs(r4 + j);

        float fa0 = va.x * sstate[ca.x], fa1 = va.y * sstate[ca.y];
        float fa2 = va.z * sstate[ca.z], fa3 = va.w * sstate[ca.w];
        float fb0 = vb.x * sstate[cb.x], fb1 = vb.y * sstate[cb.y];
        float fb2 = vb.z * sstate[cb.z], fb3 = vb.w * sstate[cb.w];

        atomicAdd(sacc + ra.x, fa0);
        atomicAdd(sacc + ra.y, fa1);
        atomicAdd(sacc + ra.z, fa2);
        atomicAdd(sacc + ra.w, fa3);
        atomicAdd(sacc + rb.x, fb0);
        atomicAdd(sacc + rb.y, fb1);
        atomicAdd(sacc + rb.z, fb2);
        atomicAdd(sacc + rb.w, fb3);
    }
    for (; i < nvec; i += stride) {
        float4 va = __ldcs(v4 + i);
        int4   ca = __ldcs(c4 + i);
        int4   ra = __ldcs(r4 + i);
        atomicAdd(sacc + ra.x, va.x * sstate[ca.x]);
        atomicAdd(sacc + ra.y, va.y * sstate[ca.y]);
        atomicAdd(sacc + ra.z, va.z * sstate[ca.z]);
        atomicAdd(sacc + ra.w, va.w * sstate[ca.w]);
    }

    // Head + tail scalars (block x==0 only, into its own sacc).
    if (blockIdx.x == 0) {
        if (threadIdx.x < head) {
            const size_t k = base + threadIdx.x;
            atomicAdd(sacc + rows[k], vals[k] * sstate[cols[k]]);
        }
        if (threadIdx.x >= 32 && threadIdx.x < 32 + tail) {
            const size_t k = base + head + ((size_t)nvec << 2) + (threadIdx.x - 32);
            atomicAdd(sacc + rows[k], vals[k] * sstate[cols[k]]);
        }
    }
    __syncthreads();

    // Flush: vector REDs (RED.E.ADD.F32x4) into the L2-resident accumulator.
    {
        float4* dst = reinterpret_cast<float4*>(g_gacc + (size_t)chunk * RES_DIM);
        const float4* src = reinterpret_cast<const float4*>(sacc);
        #pragma unroll
        for (int k = threadIdx.x; k < RES_DIM / 4; k += TPB) {
            atomicAdd(dst + k, src[k]);
        }
    }

    // Arrival protocol: order the REDs, then bump this chunk's counter.
    __threadfence();
    __syncthreads();
    if (threadIdx.x == 0) {
        unsigned int old = atomicAdd(&g_count[chunk], 1u);
        s_last = (old == BLOCKS_X - 1) ? 1u : 0u;
        if (s_last) g_count[chunk] = 0;          // restore invariant
    }
    __syncthreads();

    // Last-arriving block of this chunk: finalize (64 KB of reads total).
    // out = taylor_tanh(proj + g_gacc); then re-zero g_gacc.
    if (s_last) {
        const float t  = tanhf(1.6f);
        const float t2 = t * t;
        const float t3 = t2 * t;
        const float t4 = t2 * t2;
        const float t6 = t4 * t2;
        const float c0 = t;
        const float c1 = 1.0f - t2;
        const float c2 = t3 - t;
        const float c3 = -t4 + (4.0f / 3.0f) * t2 - (1.0f / 3.0f);
        const float c4 = (t / 3.0f) * (3.0f * t4 - 5.0f * t2 + 2.0f);
        const float c5 = -t6 + 2.0f * t4 - (17.0f / 15.0f) * t2 + (2.0f / 15.0f);

        float4* __restrict__ ga4 = reinterpret_cast<float4*>(
            g_gacc + (size_t)chunk * RES_DIM);
        const float4* __restrict__ pr4 = reinterpret_cast<const float4*>(
            proj + (size_t)chunk * RES_DIM);
        float4* __restrict__ o4 = reinterpret_cast<float4*>(
            out + (size_t)chunk * RES_DIM);

        #pragma unroll
        for (int k = threadIdx.x; k < RES_DIM / 4; k += TPB) {
            float4 z = pr4[k];
            // __ldcg: read at L2 (point of coherence for the REDs).
            float4 g = __ldcg(ga4 + k);
            z.x += g.x; z.y += g.y; z.z += g.z; z.w += g.w;
            float4 r;
            r.x = fmaf(z.x, fmaf(z.x, fmaf(z.x, fmaf(z.x, fmaf(z.x, c5, c4), c3), c2), c1), c0);
            r.y = fmaf(z.y, fmaf(z.y, fmaf(z.y, fmaf(z.y, fmaf(z.y, c5, c4), c3), c2), c1), c0);
            r.z = fmaf(z.z, fmaf(z.z, fmaf(z.z, fmaf(z.z, fmaf(z.z, c5, c4), c3), c2), c1), c0);
            r.w = fmaf(z.w, fmaf(z.w, fmaf(z.w, fmaf(z.w, fmaf(z.w, c5, c4), c3), c2), c1), c0);
            o4[k] = r;
            // Restore zero-at-entry invariant (same-thread order after the read).
            ga4[k] = make_float4(0.f, 0.f, 0.f, 0.f);
        }
    }
}

extern "C" void kernel_launch(void* const* d_in, const int* in_sizes, int n_in,
                              void* d_out, int out_size) {
    const float* proj  = (const float*)d_in[0];
    const float* state = (const float*)d_in[1];
    const float* vals  = (const float*)d_in[2];
    const int*   rows  = (const int*)d_in[3];
    const int*   cols  = (const int*)d_in[4];
    float* out = (float*)d_out;

    // 64 KB dynamic smem per block (static limit is 48 KB). Idempotent.
    cudaFuncSetAttribute(ptd_scatter_kernel,
                         cudaFuncAttributeMaxDynamicSharedMemorySize, SMEM_BYTES);

    dim3 grid(BLOCKS_X, CHUNKS);   // 288 blocks x 1024 threads, 2/SM
    ptd_scatter_kernel<<<grid, TPB, SMEM_BYTES>>>(vals, rows, cols, state, proj, out);
}